// round 1
// baseline (speedup 1.0000x reference)
#include <cuda_runtime.h>
#include <cstdint>
#include <cstddef>

#define L_SEQ 2048
#define EMB   1024
#define NB    8
#define MTOT  (NB * L_SEQ)   // 16384

// ---------------- scratch (static device arrays; no allocation) ----------------
__device__ float g_xt[(size_t)MTOT * EMB];  // tf32-rounded x
__device__ float g_w1[(size_t)EMB * EMB];   // tf32-rounded W_in
__device__ float g_w2[(size_t)EMB * EMB];   // tf32-rounded W_out
__device__ float g_v [(size_t)MTOT * EMB];  // v = x @ W_in^T (fp32)
__device__ float g_z [(size_t)MTOT * EMB];  // band-mixed v (tf32-rounded)

__device__ __forceinline__ float ftf32(float x) {
    uint32_t u;
    asm("cvt.rna.tf32.f32 %0, %1;" : "=r"(u) : "f"(x));
    return __uint_as_float(u);
}

// ---------------- tf32 pre-rounding ----------------
__global__ void cvt_tf32_kernel(const float* __restrict__ in, float* __restrict__ out, int n4) {
    int i = blockIdx.x * blockDim.x + threadIdx.x;
    if (i < n4) {
        float4 v = ((const float4*)in)[i];
        v.x = ftf32(v.x); v.y = ftf32(v.y); v.z = ftf32(v.z); v.w = ftf32(v.w);
        ((float4*)out)[i] = v;
    }
}

// ---------------- tf32 GEMM: C[M,N] = A[M,K] @ B[N,K]^T ----------------
// M=16384, N=1024, K=1024. BM=BN=128, BK=32. 256 threads, 8 warps (2x4),
// warp tile 64x32 via mma.sync.aligned.m16n8k8 tf32.

__device__ __forceinline__ void cp16(uint32_t saddr, const void* g) {
    asm volatile("cp.async.cg.shared.global [%0], [%1], 16;\n" :: "r"(saddr), "l"(g));
}

__device__ __forceinline__ void mma8(float* d, const uint32_t* a, const uint32_t* b) {
    asm volatile(
        "mma.sync.aligned.m16n8k8.row.col.f32.tf32.tf32.f32 "
        "{%0,%1,%2,%3}, {%4,%5,%6,%7}, {%8,%9}, {%0,%1,%2,%3};\n"
        : "+f"(d[0]), "+f"(d[1]), "+f"(d[2]), "+f"(d[3])
        : "r"(a[0]), "r"(a[1]), "r"(a[2]), "r"(a[3]), "r"(b[0]), "r"(b[1]));
}

__global__ void __launch_bounds__(256) gemm_tf32_kernel(
    const float* __restrict__ A, const float* __restrict__ B, float* __restrict__ C)
{
    extern __shared__ float sm[];
    constexpr int K = EMB;
    constexpr int N = EMB;
    const int m0 = blockIdx.y * 128;
    const int n0 = blockIdx.x * 128;
    const int tid = threadIdx.x;
    const int warp = tid >> 5, lane = tid & 31;
    const int wm = warp >> 2, wn = warp & 3;   // warp grid 2 (m) x 4 (n)
    const int g  = lane >> 2, tg = lane & 3;

    float acc[4][4][4];
    #pragma unroll
    for (int a = 0; a < 4; a++)
        #pragma unroll
        for (int b = 0; b < 4; b++)
            #pragma unroll
            for (int c = 0; c < 4; c++) acc[a][b][c] = 0.f;

    const int lr = tid >> 3;          // 0..31 : row within 32-row group
    const int lc = (tid & 7) << 2;    // 0,4,...,28 : float col of 16B chunk
    const uint32_t smbase = (uint32_t)__cvta_generic_to_shared(sm);

    // swizzle: element (row,col) at row*32 + (col ^ ((row&7)<<2))  (XOR on bits>=2)
    auto issue_tile = [&](int buf, int kt) {
        const float* Ag = A + (size_t)(m0 + lr) * K + kt * 32 + lc;
        const float* Bg = B + (size_t)(n0 + lr) * K + kt * 32 + lc;
        uint32_t As = smbase + (uint32_t)buf * 8192u * 4u;
        uint32_t Bs = As + 4096u * 4u;
        #pragma unroll
        for (int i = 0; i < 4; i++) {
            int r  = lr + i * 32;
            int sw = lc ^ ((r & 7) << 2);
            cp16(As + (uint32_t)(r * 32 + sw) * 4u, Ag + (size_t)i * 32 * K);
            cp16(Bs + (uint32_t)(r * 32 + sw) * 4u, Bg + (size_t)i * 32 * K);
        }
    };

    auto compute = [&](int buf) {
        const float* As = sm + buf * 8192;
        const float* Bs = As + 4096;
        #pragma unroll
        for (int ks = 0; ks < 4; ks++) {
            const int kc = ks * 8;
            uint32_t af[4][4], bf[4][2];
            #pragma unroll
            for (int mt = 0; mt < 4; mt++) {
                #pragma unroll
                for (int r = 0; r < 4; r++) {
                    int row = wm * 64 + mt * 16 + g + ((r & 1) << 3);
                    int col = kc + tg + ((r >> 1) << 2);
                    af[mt][r] = __float_as_uint(As[row * 32 + (col ^ ((row & 7) << 2))]);
                }
            }
            #pragma unroll
            for (int nt = 0; nt < 4; nt++) {
                #pragma unroll
                for (int r = 0; r < 2; r++) {
                    int row = wn * 32 + nt * 8 + g;
                    int col = kc + tg + (r << 2);
                    bf[nt][r] = __float_as_uint(Bs[row * 32 + (col ^ ((row & 7) << 2))]);
                }
            }
            #pragma unroll
            for (int mt = 0; mt < 4; mt++)
                #pragma unroll
                for (int nt = 0; nt < 4; nt++)
                    mma8(acc[mt][nt], af[mt], bf[nt]);
        }
    };

    issue_tile(0, 0);
    asm volatile("cp.async.commit_group;\n" ::: "memory");

    #pragma unroll 1
    for (int kt = 0; kt < 32; kt++) {
        int buf = kt & 1;
        if (kt + 1 < 32) {
            issue_tile(buf ^ 1, kt + 1);
            asm volatile("cp.async.commit_group;\n" ::: "memory");
            asm volatile("cp.async.wait_group 1;\n" ::: "memory");
        } else {
            asm volatile("cp.async.wait_group 0;\n" ::: "memory");
        }
        __syncthreads();
        compute(buf);
        __syncthreads();
    }

    // epilogue: fp32 stores, 2 floats per reg-pair
    #pragma unroll
    for (int mt = 0; mt < 4; mt++) {
        #pragma unroll
        for (int nt = 0; nt < 4; nt++) {
            int row = m0 + wm * 64 + mt * 16 + g;
            int col = n0 + wn * 32 + nt * 8 + (tg << 1);
            float2 v01 = make_float2(acc[mt][nt][0], acc[mt][nt][1]);
            float2 v23 = make_float2(acc[mt][nt][2], acc[mt][nt][3]);
            *(float2*)&C[(size_t)row * N + col]       = v01;
            *(float2*)&C[(size_t)(row + 8) * N + col] = v23;
        }
    }
}

// ---------------- banded Gaussian mixing along L ----------------
// z[b,q,h,p] = sum_{j in [c-7,c+7] ∩ [0,L)} w(|j-c|) v[b,j,h,p] / Z(h,q)
// heads: 0,5 -> c=q ; 1,6 -> c=q-1 ; 2,7 -> c=q+1 ; 3 -> c=0 ; 4 -> c=L-1
// Sliding 15-register window: 1 new load per output; weights are immediates.

__global__ void __launch_bounds__(128) band_kernel(const float* __restrict__ v,
                                                   float* __restrict__ z)
{
    const int p  = threadIdx.x;          // 0..127
    const int q0 = blockIdx.x * 32;
    const int h  = blockIdx.y;
    const int b  = blockIdx.z;

    const float* vp = v + (size_t)b * L_SEQ * EMB + h * 128 + p;
    float* zp       = z + ((size_t)(b * L_SEQ + q0)) * EMB + h * 128 + p;

    const float WT[15] = {
        2.28973485e-11f, 1.52299797e-08f, 3.72665317e-06f, 3.35462628e-04f,
        1.11089965e-02f, 1.35335283e-01f, 6.06530660e-01f, 1.00000000e+00f,
        6.06530660e-01f, 1.35335283e-01f, 1.11089965e-02f, 3.35462628e-04f,
        3.72665317e-06f, 1.52299797e-08f, 2.28973485e-11f };

    if (h == 3 || h == 4) {
        // constant center: one window for every query
        const int c = (h == 3) ? 0 : (L_SEQ - 1);
        float acc = 0.f, Z = 0.f;
        #pragma unroll
        for (int i = 0; i < 15; i++) {
            int j = c - 7 + i;
            if (j >= 0 && j < L_SEQ) { Z += WT[i]; acc += WT[i] * vp[(size_t)j * EMB]; }
        }
        float o = ftf32(acc / Z);
        #pragma unroll 4
        for (int qq = 0; qq < 32; qq++) zp[(size_t)qq * EMB] = o;
        return;
    }

    const int sh = (h == 0 || h == 5) ? 0 : ((h == 1 || h == 6) ? -1 : 1);
    const int cb = q0 + sh;

    float r[15];
    #pragma unroll
    for (int i = 0; i < 15; i++) {
        int j = cb - 7 + i;
        r[i] = (j >= 0 && j < L_SEQ) ? vp[(size_t)j * EMB] : 0.f;
    }

    #pragma unroll
    for (int qq = 0; qq < 32; qq++) {
        const int c = cb + qq;
        float acc = 0.f, Z = 0.f;
        #pragma unroll
        for (int i = 0; i < 15; i++) {
            int j = c - 7 + i;
            if (j >= 0 && j < L_SEQ) { Z += WT[i]; acc += WT[i] * r[(i + qq) % 15]; }
        }
        zp[(size_t)qq * EMB] = ftf32(acc / Z);
        int jn = c + 8;
        r[qq % 15] = (jn >= 0 && jn < L_SEQ) ? vp[(size_t)jn * EMB] : 0.f;
    }
}

// ---------------- launch ----------------
extern "C" void kernel_launch(void* const* d_in, const int* in_sizes, int n_in,
                              void* d_out, int out_size)
{
    const float* x   = (const float*)d_in[0];
    const float* Win = (const float*)d_in[1];
    const float* Wou = (const float*)d_in[2];
    float* out = (float*)d_out;

    float *xt, *w1, *w2, *v, *z;
    cudaGetSymbolAddress((void**)&xt, g_xt);
    cudaGetSymbolAddress((void**)&w1, g_w1);
    cudaGetSymbolAddress((void**)&w2, g_w2);
    cudaGetSymbolAddress((void**)&v,  g_v);
    cudaGetSymbolAddress((void**)&z,  g_z);

    cudaFuncSetAttribute(gemm_tf32_kernel,
                         cudaFuncAttributeMaxDynamicSharedMemorySize, 65536);

    const int nx4 = (MTOT * EMB) / 4;
    const int nw4 = (EMB * EMB) / 4;
    cvt_tf32_kernel<<<(nx4 + 255) / 256, 256>>>(x,   xt, nx4);
    cvt_tf32_kernel<<<(nw4 + 255) / 256, 256>>>(Win, w1, nw4);
    cvt_tf32_kernel<<<(nw4 + 255) / 256, 256>>>(Wou, w2, nw4);

    gemm_tf32_kernel<<<dim3(8, 128), 256, 65536>>>(xt, w1, v);
    band_kernel<<<dim3(L_SEQ / 32, 8, NB), 128>>>(v, z);
    gemm_tf32_kernel<<<dim3(8, 128), 256, 65536>>>(z, w2, out);
}

// round 3
// speedup vs baseline: 1.0738x; 1.0738x over previous
#include <cuda_runtime.h>
#include <cstdint>
#include <cstddef>

#define L_SEQ 2048
#define EMB   1024
#define NB    8
#define MTOT  (NB * L_SEQ)   // 16384

// ---------------- scratch (static device arrays; no allocation) ----------------
__device__ float g_xt[(size_t)MTOT * EMB];  // tf32-rounded, K-permuted x
__device__ float g_w1[(size_t)EMB * EMB];   // tf32-rounded, K-permuted W_in
__device__ float g_w2[(size_t)EMB * EMB];   // tf32-rounded, K-permuted W_out
__device__ float g_v [(size_t)MTOT * EMB];  // v = x @ W_in^T (fp32, natural)
__device__ float g_z [(size_t)MTOT * EMB];  // band-mixed v (tf32, K-permuted)

__device__ __forceinline__ float ftf32(float x) {
    uint32_t u;
    asm("cvt.rna.tf32.f32 %0, %1;" : "=r"(u) : "f"(x));
    return __uint_as_float(u);
}

// K-permutation within each 32-block: orig k -> pos = (k&3)*8 + ((k>>2)&1)*4 + ((k>>3)&3)
// Makes each mma thread's 8 fragment floats per BK=32 contiguous (2x LDS.128).

// ---------------- tf32 pre-rounding + K-permute ----------------
__global__ void cvt_perm_kernel(const float* __restrict__ in, float* __restrict__ out, int n4) {
    int i = blockIdx.x * blockDim.x + threadIdx.x;
    if (i < n4) {
        float4 v = ((const float4*)in)[i];
        int k = i * 4;                       // k%4 == 0: tg = 0..3 across the 4 elems
        int p = (k & ~31) + (((k >> 2) & 1) << 2) + ((k >> 3) & 3);
        out[p]      = ftf32(v.x);
        out[p + 8]  = ftf32(v.y);
        out[p + 16] = ftf32(v.z);
        out[p + 24] = ftf32(v.w);
    }
}

// =====================================================================
// tf32 mma.sync GEMM v2:  C[M,N] = A[M,K] @ B[N,K]^T  (A,B K-permuted)
// BM=BN=128, BK=32, 4-stage cp.async ring, 256 thr, warp tile 64x32.
// Fragments loaded as LDS.128 thanks to the K-permutation.
// =====================================================================

#define BM 128
#define BN 128
#define BK 32
#define NSTG 4
#define STG_B ((BM + BN) * BK * 4)   // 32768
#define GSMEM (NSTG * STG_B)         // 131072

__device__ __forceinline__ void cp16(uint32_t saddr, const void* g) {
    asm volatile("cp.async.cg.shared.global [%0], [%1], 16;\n" :: "r"(saddr), "l"(g));
}
__device__ __forceinline__ void mma8(float* d, uint32_t a0, uint32_t a1, uint32_t a2,
                                     uint32_t a3, uint32_t b0, uint32_t b1) {
    asm volatile(
        "mma.sync.aligned.m16n8k8.row.col.f32.tf32.tf32.f32 "
        "{%0,%1,%2,%3}, {%4,%5,%6,%7}, {%8,%9}, {%0,%1,%2,%3};\n"
        : "+f"(d[0]), "+f"(d[1]), "+f"(d[2]), "+f"(d[3])
        : "r"(a0), "r"(a1), "r"(a2), "r"(a3), "r"(b0), "r"(b1));
}

__global__ void __launch_bounds__(256) gemm_tf32_v2(
    const float* __restrict__ A, const float* __restrict__ B, float* __restrict__ C)
{
    extern __shared__ float smf[];
    char* smc = (char*)smf;
    constexpr int K = EMB;
    const int tid  = threadIdx.x;
    const int warp = tid >> 5, lane = tid & 31;
    const int wm = warp >> 2, wn = warp & 3;   // 2 (m) x 4 (n)
    const int g  = lane >> 2, tg = lane & 3;
    const int m0 = blockIdx.y * BM;
    const int n0 = blockIdx.x * BN;

    float acc[4][4][4];
    #pragma unroll
    for (int a = 0; a < 4; a++)
        #pragma unroll
        for (int b = 0; b < 4; b++)
            #pragma unroll
            for (int c = 0; c < 4; c++) acc[a][b][c] = 0.f;

    // ---- loader: 8 chunks of 16B per thread per kt, hoisted addressing ----
    const int lr  = tid >> 3;        // row 0..31 (A and B both 128 rows, 4 groups)
    const int lcc = tid & 7;         // chunk 0..7
    const float* Ag = A + (size_t)(m0 + lr) * K + lcc * 4;
    const float* Bg = B + (size_t)(n0 + lr) * K + lcc * 4;
    const uint32_t smb  = (uint32_t)__cvta_generic_to_shared(smf);
    const uint32_t stoff = (uint32_t)(lr * 128 + ((lcc ^ (lr & 7)) << 4));

    auto loadst = [&](int s) {
        uint32_t sa = smb + (uint32_t)s * STG_B + stoff;
        uint32_t sb = sa + BM * BK * 4;
        #pragma unroll
        for (int i = 0; i < 4; i++) cp16(sa + i * 4096u, Ag + (size_t)i * 32 * K);
        #pragma unroll
        for (int i = 0; i < 4; i++) cp16(sb + i * 4096u, Bg + (size_t)i * 32 * K);
        Ag += BK; Bg += BK;
        asm volatile("cp.async.commit_group;\n" ::: "memory");
    };

    // ---- per-thread fragment byte offsets (within stage) ----
    const uint32_t c0 = (uint32_t)(((2 * tg)     ^ g) << 4);
    const uint32_t c1 = (uint32_t)(((2 * tg + 1) ^ g) << 4);

    auto compute = [&](int s) {
        const char* stg = smc + (size_t)s * STG_B;
        float4 av[4][2][2], bv[4][2];
        #pragma unroll
        for (int mt = 0; mt < 4; mt++)
            #pragma unroll
            for (int rh = 0; rh < 2; rh++) {
                const char* rp = stg + (wm * 64 + mt * 16 + rh * 8 + g) * 128;
                av[mt][rh][0] = *(const float4*)(rp + c0);
                av[mt][rh][1] = *(const float4*)(rp + c1);
            }
        #pragma unroll
        for (int nt = 0; nt < 4; nt++) {
            const char* rp = stg + 16384 + (wn * 32 + nt * 8 + g) * 128;
            bv[nt][0] = *(const float4*)(rp + c0);
            bv[nt][1] = *(const float4*)(rp + c1);
        }
        #pragma unroll
        for (int ks = 0; ks < 4; ks++) {
            #pragma unroll
            for (int mt = 0; mt < 4; mt++) {
                uint32_t a0 = __float_as_uint(((const float*)&av[mt][0][0])[ks]);
                uint32_t a1 = __float_as_uint(((const float*)&av[mt][1][0])[ks]);
                uint32_t a2 = __float_as_uint(((const float*)&av[mt][0][1])[ks]);
                uint32_t a3 = __float_as_uint(((const float*)&av[mt][1][1])[ks]);
                #pragma unroll
                for (int nt = 0; nt < 4; nt++) {
                    uint32_t b0 = __float_as_uint(((const float*)&bv[nt][0])[ks]);
                    uint32_t b1 = __float_as_uint(((const float*)&bv[nt][1])[ks]);
                    mma8(acc[mt][nt], a0, a1, a2, a3, b0, b1);
                }
            }
        }
    };

    // ---- 4-stage pipeline, one __syncthreads per kt ----
    loadst(0); loadst(1); loadst(2);

    #pragma unroll 1
    for (int kt = 0; kt < 32; kt++) {
        asm volatile("cp.async.wait_group 2;\n" ::: "memory");
        __syncthreads();
        if (kt < 29) loadst((kt + 3) & 3);
        else asm volatile("cp.async.commit_group;\n" ::: "memory");
        compute(kt & 3);
    }

    // ---- epilogue ----
    #pragma unroll
    for (int mt = 0; mt < 4; mt++) {
        #pragma unroll
        for (int nt = 0; nt < 4; nt++) {
            int row = m0 + wm * 64 + mt * 16 + g;
            int col = n0 + wn * 32 + nt * 8 + (tg << 1);
            *(float2*)&C[(size_t)row * EMB + col] =
                make_float2(acc[mt][nt][0], acc[mt][nt][1]);
            *(float2*)&C[(size_t)(row + 8) * EMB + col] =
                make_float2(acc[mt][nt][2], acc[mt][nt][3]);
        }
    }
}

// ---------------- banded Gaussian mixing along L ----------------
// z[b,q,h,p] = sum_{j in [c-7,c+7] ∩ [0,L)} w(|j-c|) v[b,j,h,p] / Z(h,q)
// heads: 0,5 -> c=q ; 1,6 -> c=q-1 ; 2,7 -> c=q+1 ; 3 -> c=0 ; 4 -> c=L-1
// Output written tf32-rounded AND K-permuted (it is GEMM2's A operand).

__global__ void __launch_bounds__(128) band_kernel(const float* __restrict__ v,
                                                   float* __restrict__ z)
{
    const int p  = threadIdx.x;          // 0..127
    const int q0 = blockIdx.x * 32;
    const int h  = blockIdx.y;
    const int b  = blockIdx.z;

    const float* vp = v + (size_t)b * L_SEQ * EMB + h * 128 + p;
    const int c_  = h * 128 + p;
    const int pc  = (c_ & ~31) + ((c_ & 3) << 3) + (((c_ >> 2) & 1) << 2) + ((c_ >> 3) & 3);
    float* zp = z + ((size_t)(b * L_SEQ + q0)) * EMB + pc;

    const float WT[15] = {
        2.28973485e-11f, 1.52299797e-08f, 3.72665317e-06f, 3.35462628e-04f,
        1.11089965e-02f, 1.35335283e-01f, 6.06530660e-01f, 1.00000000e+00f,
        6.06530660e-01f, 1.35335283e-01f, 1.11089965e-02f, 3.35462628e-04f,
        3.72665317e-06f, 1.52299797e-08f, 2.28973485e-11f };

    if (h == 3 || h == 4) {
        const int c = (h == 3) ? 0 : (L_SEQ - 1);
        float acc = 0.f, Z = 0.f;
        #pragma unroll
        for (int i = 0; i < 15; i++) {
            int j = c - 7 + i;
            if (j >= 0 && j < L_SEQ) { Z += WT[i]; acc += WT[i] * vp[(size_t)j * EMB]; }
        }
        float o = ftf32(acc / Z);
        #pragma unroll 4
        for (int qq = 0; qq < 32; qq++) zp[(size_t)qq * EMB] = o;
        return;
    }

    const int sh = (h == 0 || h == 5) ? 0 : ((h == 1 || h == 6) ? -1 : 1);
    const int cb = q0 + sh;

    float r[15];
    #pragma unroll
    for (int i = 0; i < 15; i++) {
        int j = cb - 7 + i;
        r[i] = (j >= 0 && j < L_SEQ) ? vp[(size_t)j * EMB] : 0.f;
    }

    #pragma unroll
    for (int qq = 0; qq < 32; qq++) {
        const int c = cb + qq;
        float acc = 0.f, Z = 0.f;
        #pragma unroll
        for (int i = 0; i < 15; i++) {
            int j = c - 7 + i;
            if (j >= 0 && j < L_SEQ) { Z += WT[i]; acc += WT[i] * r[(i + qq) % 15]; }
        }
        zp[(size_t)qq * EMB] = ftf32(acc / Z);
        int jn = c + 8;
        r[qq % 15] = (jn >= 0 && jn < L_SEQ) ? vp[(size_t)jn * EMB] : 0.f;
    }
}

// ---------------- launch ----------------
extern "C" void kernel_launch(void* const* d_in, const int* in_sizes, int n_in,
                              void* d_out, int out_size)
{
    const float* x   = (const float*)d_in[0];
    const float* Win = (const float*)d_in[1];
    const float* Wou = (const float*)d_in[2];
    float* out = (float*)d_out;

    float *xt, *w1, *w2, *v, *z;
    cudaGetSymbolAddress((void**)&xt, g_xt);
    cudaGetSymbolAddress((void**)&w1, g_w1);
    cudaGetSymbolAddress((void**)&w2, g_w2);
    cudaGetSymbolAddress((void**)&v,  g_v);
    cudaGetSymbolAddress((void**)&z,  g_z);

    cudaFuncSetAttribute(gemm_tf32_v2,
                         cudaFuncAttributeMaxDynamicSharedMemorySize, GSMEM);

    const int nx4 = (MTOT * EMB) / 4;
    const int nw4 = (EMB * EMB) / 4;
    cvt_perm_kernel<<<(nx4 + 255) / 256, 256>>>(x,   xt, nx4);
    cvt_perm_kernel<<<(nw4 + 255) / 256, 256>>>(Win, w1, nw4);
    cvt_perm_kernel<<<(nw4 + 255) / 256, 256>>>(Wou, w2, nw4);

    gemm_tf32_v2<<<dim3(EMB / BN, MTOT / BM), 256, GSMEM>>>(xt, w1, v);
    band_kernel<<<dim3(L_SEQ / 32, 8, NB), 128>>>(v, z);
    gemm_tf32_v2<<<dim3(EMB / BN, MTOT / BM), 256, GSMEM>>>(z, w2, out);
}

// round 4
// speedup vs baseline: 1.1007x; 1.0251x over previous
#include <cuda_runtime.h>
#include <cstdint>
#include <cstddef>

#define L_SEQ 2048
#define EMB   1024
#define NB    8
#define MTOT  (NB * L_SEQ)   // 16384

// ---------------- scratch (static device arrays; no allocation) ----------------
__device__ float g_xt[(size_t)MTOT * EMB];  // tf32-rounded, K-permuted x
__device__ float g_w1[(size_t)EMB * EMB];   // tf32-rounded, K-permuted W_in
__device__ float g_w2[(size_t)EMB * EMB];   // tf32-rounded, K-permuted W_out
__device__ float g_v [(size_t)MTOT * EMB];  // v = x @ W_in^T (fp32, natural)
__device__ float g_z [(size_t)MTOT * EMB];  // band-mixed v (tf32, K-permuted)

__device__ __forceinline__ float ftf32(float x) {
    uint32_t u;
    asm("cvt.rna.tf32.f32 %0, %1;" : "=r"(u) : "f"(x));
    return __uint_as_float(u);
}

// K-permutation within each 32-block: orig k -> pos = (k&3)*8 + ((k>>2)&1)*4 + ((k>>3)&3)
// Per mma thread, the 8 fragment floats of a BK=32 iteration become two float4s.

// ---------------- tf32 pre-rounding + K-permute ----------------
__global__ void cvt_perm_kernel(const float* __restrict__ in, float* __restrict__ out, int n4) {
    int i = blockIdx.x * blockDim.x + threadIdx.x;
    if (i < n4) {
        float4 v = ((const float4*)in)[i];
        int k = i * 4;
        int p = (k & ~31) + (((k >> 2) & 1) << 2) + ((k >> 3) & 3);
        out[p]      = ftf32(v.x);
        out[p + 8]  = ftf32(v.y);
        out[p + 16] = ftf32(v.z);
        out[p + 24] = ftf32(v.w);
    }
}

// =====================================================================
// tf32 mma.sync GEMM v3:  C[M,N] = A[M,K] @ B[N,K]^T  (A,B K-permuted)
// BM=BN=128, BK=32, 4-stage cp.async ring, 512 threads (16 warps, 4x4),
// warp tile 32x32. Occupancy-oriented: 4 warps/SMSP to hide LDS+mma latency.
// =====================================================================

#define BM 128
#define BN 128
#define BK 32
#define NSTG 4
#define STG_B ((BM + BN) * BK * 4)   // 32768
#define GSMEM (NSTG * STG_B)         // 131072

__device__ __forceinline__ void cp16(uint32_t saddr, const void* g) {
    asm volatile("cp.async.cg.shared.global [%0], [%1], 16;\n" :: "r"(saddr), "l"(g));
}
__device__ __forceinline__ void mma8(float* d, uint32_t a0, uint32_t a1, uint32_t a2,
                                     uint32_t a3, uint32_t b0, uint32_t b1) {
    asm volatile(
        "mma.sync.aligned.m16n8k8.row.col.f32.tf32.tf32.f32 "
        "{%0,%1,%2,%3}, {%4,%5,%6,%7}, {%8,%9}, {%0,%1,%2,%3};\n"
        : "+f"(d[0]), "+f"(d[1]), "+f"(d[2]), "+f"(d[3])
        : "r"(a0), "r"(a1), "r"(a2), "r"(a3), "r"(b0), "r"(b1));
}

__global__ void __launch_bounds__(512, 1) gemm_tf32_v3(
    const float* __restrict__ A, const float* __restrict__ B, float* __restrict__ C)
{
    extern __shared__ float smf[];
    char* smc = (char*)smf;
    constexpr int K = EMB;
    const int tid  = threadIdx.x;
    const int warp = tid >> 5, lane = tid & 31;
    const int wm = warp >> 2, wn = warp & 3;   // 4 (m) x 4 (n)
    const int g  = lane >> 2, tg = lane & 3;
    const int m0 = blockIdx.y * BM;
    const int n0 = blockIdx.x * BN;

    float acc[2][4][4];
    #pragma unroll
    for (int a = 0; a < 2; a++)
        #pragma unroll
        for (int b = 0; b < 4; b++)
            #pragma unroll
            for (int c = 0; c < 4; c++) acc[a][b][c] = 0.f;

    // ---- loader: 4 chunks of 16B per thread per stage ----
    const int lr  = tid >> 3;        // 0..63
    const int lcc = tid & 7;         // 0..7
    const float* Ag = A + (size_t)(m0 + lr) * K + lcc * 4;
    const float* Bg = B + (size_t)(n0 + lr) * K + lcc * 4;
    const uint32_t smb   = (uint32_t)__cvta_generic_to_shared(smf);
    const uint32_t stoff = (uint32_t)(lr * 128 + ((lcc ^ (lr & 7)) << 4));

    auto loadst = [&](int s) {
        uint32_t sa = smb + (uint32_t)s * STG_B + stoff;
        uint32_t sb = sa + (uint32_t)(BM * BK * 4);
        cp16(sa,             Ag);
        cp16(sa + 64u * 128u, Ag + (size_t)64 * K);
        cp16(sb,             Bg);
        cp16(sb + 64u * 128u, Bg + (size_t)64 * K);
        Ag += BK; Bg += BK;
        asm volatile("cp.async.commit_group;\n" ::: "memory");
    };

    // ---- per-thread fragment byte offsets (within a 128B row) ----
    const uint32_t c0 = (uint32_t)(((2 * tg)     ^ g) << 4);
    const uint32_t c1 = (uint32_t)(((2 * tg + 1) ^ g) << 4);

    auto compute = [&](int s) {
        const char* stg = smc + (size_t)s * STG_B;
        float4 av[2][2][2], bv[4][2];
        #pragma unroll
        for (int mt = 0; mt < 2; mt++)
            #pragma unroll
            for (int rh = 0; rh < 2; rh++) {
                const char* rp = stg + (wm * 32 + mt * 16 + rh * 8 + g) * 128;
                av[mt][rh][0] = *(const float4*)(rp + c0);
                av[mt][rh][1] = *(const float4*)(rp + c1);
            }
        #pragma unroll
        for (int nt = 0; nt < 4; nt++) {
            const char* rp = stg + BM * BK * 4 + (wn * 32 + nt * 8 + g) * 128;
            bv[nt][0] = *(const float4*)(rp + c0);
            bv[nt][1] = *(const float4*)(rp + c1);
        }
        #pragma unroll
        for (int ks = 0; ks < 4; ks++) {
            #pragma unroll
            for (int mt = 0; mt < 2; mt++) {
                uint32_t a0 = __float_as_uint(((const float*)&av[mt][0][0])[ks]);
                uint32_t a1 = __float_as_uint(((const float*)&av[mt][1][0])[ks]);
                uint32_t a2 = __float_as_uint(((const float*)&av[mt][0][1])[ks]);
                uint32_t a3 = __float_as_uint(((const float*)&av[mt][1][1])[ks]);
                #pragma unroll
                for (int nt = 0; nt < 4; nt++) {
                    uint32_t b0 = __float_as_uint(((const float*)&bv[nt][0])[ks]);
                    uint32_t b1 = __float_as_uint(((const float*)&bv[nt][1])[ks]);
                    mma8(acc[mt][nt], a0, a1, a2, a3, b0, b1);
                }
            }
        }
    };

    // ---- 4-stage pipeline, one __syncthreads per kt ----
    loadst(0); loadst(1); loadst(2);

    #pragma unroll 1
    for (int kt = 0; kt < 32; kt++) {
        asm volatile("cp.async.wait_group 2;\n" ::: "memory");
        __syncthreads();
        if (kt < 29) loadst((kt + 3) & 3);
        else asm volatile("cp.async.commit_group;\n" ::: "memory");
        compute(kt & 3);
    }

    // ---- epilogue ----
    #pragma unroll
    for (int mt = 0; mt < 2; mt++) {
        #pragma unroll
        for (int nt = 0; nt < 4; nt++) {
            int row = m0 + wm * 32 + mt * 16 + g;
            int col = n0 + wn * 32 + nt * 8 + (tg << 1);
            *(float2*)&C[(size_t)row * EMB + col] =
                make_float2(acc[mt][nt][0], acc[mt][nt][1]);
            *(float2*)&C[(size_t)(row + 8) * EMB + col] =
                make_float2(acc[mt][nt][2], acc[mt][nt][3]);
        }
    }
}

// ---------------- banded Gaussian mixing along L ----------------
// z[b,q,h,p] = sum_{j in [c-7,c+7] ∩ [0,L)} w(|j-c|) v[b,j,h,p] / Z(h,q)
// heads: 0,5 -> c=q ; 1,6 -> c=q-1 ; 2,7 -> c=q+1 ; 3 -> c=0 ; 4 -> c=L-1
// Output written tf32-rounded AND K-permuted (it is GEMM2's A operand).

__global__ void __launch_bounds__(128) band_kernel(const float* __restrict__ v,
                                                   float* __restrict__ z)
{
    const int p  = threadIdx.x;          // 0..127
    const int q0 = blockIdx.x * 32;
    const int h  = blockIdx.y;
    const int b  = blockIdx.z;

    const float* vp = v + (size_t)b * L_SEQ * EMB + h * 128 + p;
    const int c_  = h * 128 + p;
    const int pc  = (c_ & ~31) + ((c_ & 3) << 3) + (((c_ >> 2) & 1) << 2) + ((c_ >> 3) & 3);
    float* zp = z + ((size_t)(b * L_SEQ + q0)) * EMB + pc;

    const float WT[15] = {
        2.28973485e-11f, 1.52299797e-08f, 3.72665317e-06f, 3.35462628e-04f,
        1.11089965e-02f, 1.35335283e-01f, 6.06530660e-01f, 1.00000000e+00f,
        6.06530660e-01f, 1.35335283e-01f, 1.11089965e-02f, 3.35462628e-04f,
        3.72665317e-06f, 1.52299797e-08f, 2.28973485e-11f };

    if (h == 3 || h == 4) {
        const int c = (h == 3) ? 0 : (L_SEQ - 1);
        float acc = 0.f, Z = 0.f;
        #pragma unroll
        for (int i = 0; i < 15; i++) {
            int j = c - 7 + i;
            if (j >= 0 && j < L_SEQ) { Z += WT[i]; acc += WT[i] * vp[(size_t)j * EMB]; }
        }
        float o = ftf32(acc / Z);
        #pragma unroll 4
        for (int qq = 0; qq < 32; qq++) zp[(size_t)qq * EMB] = o;
        return;
    }

    const int sh = (h == 0 || h == 5) ? 0 : ((h == 1 || h == 6) ? -1 : 1);
    const int cb = q0 + sh;

    float r[15];
    #pragma unroll
    for (int i = 0; i < 15; i++) {
        int j = cb - 7 + i;
        r[i] = (j >= 0 && j < L_SEQ) ? vp[(size_t)j * EMB] : 0.f;
    }

    #pragma unroll
    for (int qq = 0; qq < 32; qq++) {
        const int c = cb + qq;
        float acc = 0.f, Z = 0.f;
        #pragma unroll
        for (int i = 0; i < 15; i++) {
            int j = c - 7 + i;
            if (j >= 0 && j < L_SEQ) { Z += WT[i]; acc += WT[i] * r[(i + qq) % 15]; }
        }
        zp[(size_t)qq * EMB] = ftf32(acc / Z);
        int jn = c + 8;
        r[qq % 15] = (jn >= 0 && jn < L_SEQ) ? vp[(size_t)jn * EMB] : 0.f;
    }
}

// ---------------- launch ----------------
extern "C" void kernel_launch(void* const* d_in, const int* in_sizes, int n_in,
                              void* d_out, int out_size)
{
    const float* x   = (const float*)d_in[0];
    const float* Win = (const float*)d_in[1];
    const float* Wou = (const float*)d_in[2];
    float* out = (float*)d_out;

    float *xt, *w1, *w2, *v, *z;
    cudaGetSymbolAddress((void**)&xt, g_xt);
    cudaGetSymbolAddress((void**)&w1, g_w1);
    cudaGetSymbolAddress((void**)&w2, g_w2);
    cudaGetSymbolAddress((void**)&v,  g_v);
    cudaGetSymbolAddress((void**)&z,  g_z);

    cudaFuncSetAttribute(gemm_tf32_v3,
                         cudaFuncAttributeMaxDynamicSharedMemorySize, GSMEM);

    const int nx4 = (MTOT * EMB) / 4;
    const int nw4 = (EMB * EMB) / 4;
    cvt_perm_kernel<<<(nx4 + 255) / 256, 256>>>(x,   xt, nx4);
    cvt_perm_kernel<<<(nw4 + 255) / 256, 256>>>(Win, w1, nw4);
    cvt_perm_kernel<<<(nw4 + 255) / 256, 256>>>(Wou, w2, nw4);

    gemm_tf32_v3<<<dim3(EMB / BN, MTOT / BM), 512, GSMEM>>>(xt, w1, v);
    band_kernel<<<dim3(L_SEQ / 32, 8, NB), 128>>>(v, z);
    gemm_tf32_v3<<<dim3(EMB / BN, MTOT / BM), 512, GSMEM>>>(z, w2, out);
}

// round 5
// speedup vs baseline: 1.2704x; 1.1541x over previous
#include <cuda_runtime.h>
#include <cuda_fp16.h>
#include <cstdint>
#include <cstddef>

#define L_SEQ 2048
#define EMB   1024
#define NB    8
#define MTOT  (NB * L_SEQ)   // 16384

// ---------------- scratch (static device arrays; no allocation) ----------------
__device__ __half g_xt[(size_t)MTOT * EMB];  // fp16, K-permuted x
__device__ __half g_w1[(size_t)EMB * EMB];   // fp16, K-permuted W_in
__device__ __half g_w2[(size_t)EMB * EMB];   // fp16, K-permuted W_out
__device__ float  g_v [(size_t)MTOT * EMB];  // v = x @ W_in^T (fp32, natural)
__device__ __half g_z [(size_t)MTOT * EMB];  // band-mixed v (fp16, K-permuted)

// K-permutation on k-PAIRS within each 64-element K block:
//   q = (k>>1) & 31 ;  p = (q&3)*8 + ((q>>2)&1)*4 + (q>>3)
// Puts each mma thread's m16n8k16 fragment pairs for a whole BK=64 into
// 16B chunks 2*tg and 2*tg+1 of the 128-byte row (2x LDS.128 per row).

// ---------------- fp32 -> fp16 conversion + K-permute ----------------
__global__ void cvt_perm_h(const float* __restrict__ in, __half* __restrict__ out, int n4) {
    int i = blockIdx.x * blockDim.x + threadIdx.x;
    if (i < n4) {
        float4 v = ((const float4*)in)[i];
        int k  = i * 4;
        int kb = k & ~63;               // 64-elem block base
        int q  = (k >> 1) & 31;         // even pair index
        int p1 = (q & 3) * 8 + ((q >> 2) & 1) * 4 + (q >> 3);
        int q2 = q + 1;
        int p2 = (q2 & 3) * 8 + ((q2 >> 2) & 1) * 4 + (q2 >> 3);
        __half2* o = (__half2*)out;
        o[(kb >> 1) + p1] = __floats2half2_rn(v.x, v.y);
        o[(kb >> 1) + p2] = __floats2half2_rn(v.z, v.w);
    }
}

// =====================================================================
// fp16 mma.sync GEMM:  C[M,N] = A[M,K] @ B[N,K]^T   (A,B fp16 K-permuted)
// BM=BN=128, BK=64, 4-stage cp.async ring, 512 threads (16 warps, 4x4),
// warp tile 32x32 via mma.sync.m16n8k16.f32.f16.f16.f32 (fp32 accum).
// =====================================================================

#define BM 128
#define BN 128
#define BK 64
#define NSTG 4
#define STG_B ((BM + BN) * BK * 2)   // 32768 bytes
#define GSMEM (NSTG * STG_B)         // 131072

__device__ __forceinline__ void cp16(uint32_t saddr, const void* g) {
    asm volatile("cp.async.cg.shared.global [%0], [%1], 16;\n" :: "r"(saddr), "l"(g));
}
__device__ __forceinline__ void mma16(float* d, uint32_t a0, uint32_t a1, uint32_t a2,
                                      uint32_t a3, uint32_t b0, uint32_t b1) {
    asm volatile(
        "mma.sync.aligned.m16n8k16.row.col.f32.f16.f16.f32 "
        "{%0,%1,%2,%3}, {%4,%5,%6,%7}, {%8,%9}, {%0,%1,%2,%3};\n"
        : "+f"(d[0]), "+f"(d[1]), "+f"(d[2]), "+f"(d[3])
        : "r"(a0), "r"(a1), "r"(a2), "r"(a3), "r"(b0), "r"(b1));
}

__global__ void __launch_bounds__(512, 1) gemm_f16_v4(
    const __half* __restrict__ A, const __half* __restrict__ B, float* __restrict__ C)
{
    extern __shared__ char smc[];
    constexpr int K = EMB;
    const int tid  = threadIdx.x;
    const int warp = tid >> 5, lane = tid & 31;
    const int wm = warp >> 2, wn = warp & 3;   // 4 (m) x 4 (n)
    const int g  = lane >> 2, tg = lane & 3;
    const int m0 = blockIdx.y * BM;
    const int n0 = blockIdx.x * BN;

    float acc[2][4][4];
    #pragma unroll
    for (int a = 0; a < 2; a++)
        #pragma unroll
        for (int b = 0; b < 4; b++)
            #pragma unroll
            for (int c = 0; c < 4; c++) acc[a][b][c] = 0.f;

    // ---- loader: 4 cp.async of 16B per thread per stage ----
    const int lr  = tid >> 3;        // 0..63
    const int lcc = tid & 7;         // chunk 0..7 (16B = 8 halves each)
    const __half* Ag = A + (size_t)(m0 + lr) * K + lcc * 8;
    const __half* Bg = B + (size_t)(n0 + lr) * K + lcc * 8;
    const uint32_t smb   = (uint32_t)__cvta_generic_to_shared(smc);
    const uint32_t stoff = (uint32_t)(lr * 128 + ((lcc ^ (lr & 7)) << 4));

    auto loadst = [&](int s) {
        uint32_t sa = smb + (uint32_t)s * STG_B + stoff;
        uint32_t sb = sa + (uint32_t)(BM * BK * 2);
        cp16(sa,              Ag);
        cp16(sa + 64u * 128u, Ag + (size_t)64 * K);
        cp16(sb,              Bg);
        cp16(sb + 64u * 128u, Bg + (size_t)64 * K);
        Ag += BK; Bg += BK;
        asm volatile("cp.async.commit_group;\n" ::: "memory");
    };

    // per-thread fragment chunk offsets within a 128B row (swizzled)
    const uint32_t c0 = (uint32_t)(((2 * tg)     ^ g) << 4);
    const uint32_t c1 = (uint32_t)(((2 * tg + 1) ^ g) << 4);

    auto compute = [&](int s) {
        const char* stg = smc + (size_t)s * STG_B;
        float4 av[2][2][2], bv[4][2];
        #pragma unroll
        for (int mt = 0; mt < 2; mt++)
            #pragma unroll
            for (int rh = 0; rh < 2; rh++) {
                const char* rp = stg + (wm * 32 + mt * 16 + rh * 8 + g) * 128;
                av[mt][rh][0] = *(const float4*)(rp + c0);
                av[mt][rh][1] = *(const float4*)(rp + c1);
            }
        #pragma unroll
        for (int nt = 0; nt < 4; nt++) {
            const char* rp = stg + BM * BK * 2 + (wn * 32 + nt * 8 + g) * 128;
            bv[nt][0] = *(const float4*)(rp + c0);
            bv[nt][1] = *(const float4*)(rp + c1);
        }
        #pragma unroll
        for (int ks = 0; ks < 4; ks++) {
            #pragma unroll
            for (int mt = 0; mt < 2; mt++) {
                uint32_t a0 = __float_as_uint(((const float*)&av[mt][0][0])[ks]);
                uint32_t a1 = __float_as_uint(((const float*)&av[mt][1][0])[ks]);
                uint32_t a2 = __float_as_uint(((const float*)&av[mt][0][1])[ks]);
                uint32_t a3 = __float_as_uint(((const float*)&av[mt][1][1])[ks]);
                #pragma unroll
                for (int nt = 0; nt < 4; nt++) {
                    uint32_t b0 = __float_as_uint(((const float*)&bv[nt][0])[ks]);
                    uint32_t b1 = __float_as_uint(((const float*)&bv[nt][1])[ks]);
                    mma16(acc[mt][nt], a0, a1, a2, a3, b0, b1);
                }
            }
        }
    };

    // ---- 4-stage pipeline over 16 K-iterations ----
    loadst(0); loadst(1); loadst(2);

    #pragma unroll 1
    for (int kt = 0; kt < 16; kt++) {
        asm volatile("cp.async.wait_group 2;\n" ::: "memory");
        __syncthreads();
        if (kt < 13) loadst((kt + 3) & 3);
        else asm volatile("cp.async.commit_group;\n" ::: "memory");
        compute(kt & 3);
    }

    // ---- epilogue (fp32 accumulators -> fp32 C) ----
    #pragma unroll
    for (int mt = 0; mt < 2; mt++) {
        #pragma unroll
        for (int nt = 0; nt < 4; nt++) {
            int row = m0 + wm * 32 + mt * 16 + g;
            int col = n0 + wn * 32 + nt * 8 + (tg << 1);
            *(float2*)&C[(size_t)row * EMB + col] =
                make_float2(acc[mt][nt][0], acc[mt][nt][1]);
            *(float2*)&C[(size_t)(row + 8) * EMB + col] =
                make_float2(acc[mt][nt][2], acc[mt][nt][3]);
        }
    }
}

// ---------------- banded Gaussian mixing along L ----------------
// z[b,q,h,p] = sum_{j in [c-7,c+7] ∩ [0,L)} w(|j-c|) v[b,j,h,p] / Z(h,q)
// heads: 0,5 -> c=q ; 1,6 -> c=q-1 ; 2,7 -> c=q+1 ; 3 -> c=0 ; 4 -> c=L-1
// Output written fp16 AND K-permuted (it is GEMM2's A operand).

__global__ void __launch_bounds__(128) band_kernel(const float* __restrict__ v,
                                                   __half* __restrict__ z)
{
    const int p  = threadIdx.x;          // 0..127
    const int q0 = blockIdx.x * 32;
    const int h  = blockIdx.y;
    const int b  = blockIdx.z;

    const float* vp = v + (size_t)b * L_SEQ * EMB + h * 128 + p;
    const int c_ = h * 128 + p;
    const int qq_ = (c_ >> 1) & 31;
    const int pp  = (qq_ & 3) * 8 + ((qq_ >> 2) & 1) * 4 + (qq_ >> 3);
    const int pc  = (c_ & ~63) + pp * 2 + (c_ & 1);
    __half* zp = z + ((size_t)(b * L_SEQ + q0)) * EMB + pc;

    const float WT[15] = {
        2.28973485e-11f, 1.52299797e-08f, 3.72665317e-06f, 3.35462628e-04f,
        1.11089965e-02f, 1.35335283e-01f, 6.06530660e-01f, 1.00000000e+00f,
        6.06530660e-01f, 1.35335283e-01f, 1.11089965e-02f, 3.35462628e-04f,
        3.72665317e-06f, 1.52299797e-08f, 2.28973485e-11f };

    if (h == 3 || h == 4) {
        const int c = (h == 3) ? 0 : (L_SEQ - 1);
        float acc = 0.f, Z = 0.f;
        #pragma unroll
        for (int i = 0; i < 15; i++) {
            int j = c - 7 + i;
            if (j >= 0 && j < L_SEQ) { Z += WT[i]; acc += WT[i] * vp[(size_t)j * EMB]; }
        }
        __half o = __float2half_rn(acc / Z);
        #pragma unroll 4
        for (int qq = 0; qq < 32; qq++) zp[(size_t)qq * EMB] = o;
        return;
    }

    const int sh = (h == 0 || h == 5) ? 0 : ((h == 1 || h == 6) ? -1 : 1);
    const int cb = q0 + sh;

    float r[15];
    #pragma unroll
    for (int i = 0; i < 15; i++) {
        int j = cb - 7 + i;
        r[i] = (j >= 0 && j < L_SEQ) ? vp[(size_t)j * EMB] : 0.f;
    }

    #pragma unroll
    for (int qq = 0; qq < 32; qq++) {
        const int c = cb + qq;
        float acc = 0.f, Z = 0.f;
        #pragma unroll
        for (int i = 0; i < 15; i++) {
            int j = c - 7 + i;
            if (j >= 0 && j < L_SEQ) { Z += WT[i]; acc += WT[i] * r[(i + qq) % 15]; }
        }
        zp[(size_t)qq * EMB] = __float2half_rn(acc / Z);
        int jn = c + 8;
        r[qq % 15] = (jn >= 0 && jn < L_SEQ) ? vp[(size_t)jn * EMB] : 0.f;
    }
}

// ---------------- launch ----------------
extern "C" void kernel_launch(void* const* d_in, const int* in_sizes, int n_in,
                              void* d_out, int out_size)
{
    const float* x   = (const float*)d_in[0];
    const float* Win = (const float*)d_in[1];
    const float* Wou = (const float*)d_in[2];
    float* out = (float*)d_out;

    __half *xt, *w1, *w2, *z;
    float *v;
    cudaGetSymbolAddress((void**)&xt, g_xt);
    cudaGetSymbolAddress((void**)&w1, g_w1);
    cudaGetSymbolAddress((void**)&w2, g_w2);
    cudaGetSymbolAddress((void**)&v,  g_v);
    cudaGetSymbolAddress((void**)&z,  g_z);

    cudaFuncSetAttribute(gemm_f16_v4,
                         cudaFuncAttributeMaxDynamicSharedMemorySize, GSMEM);

    const int nx4 = (MTOT * EMB) / 4;
    const int nw4 = (EMB * EMB) / 4;
    cvt_perm_h<<<(nx4 + 255) / 256, 256>>>(x,   xt, nx4);
    cvt_perm_h<<<(nw4 + 255) / 256, 256>>>(Win, w1, nw4);
    cvt_perm_h<<<(nw4 + 255) / 256, 256>>>(Wou, w2, nw4);

    gemm_f16_v4<<<dim3(EMB / BN, MTOT / BM), 512, GSMEM>>>(xt, w1, v);
    band_kernel<<<dim3(L_SEQ / 32, 8, NB), 128>>>(v, z);
    gemm_f16_v4<<<dim3(EMB / BN, MTOT / BM), 512, GSMEM>>>(z, w2, out);
}

// round 6
// speedup vs baseline: 2.1511x; 1.6932x over previous
#include <cuda_runtime.h>
#include <cuda_fp16.h>
#include <cstdint>
#include <cstddef>

#define L_SEQ 2048
#define EMB   1024
#define NB    8
#define MTOT  (NB * L_SEQ)   // 16384

// ---------------- scratch (static device arrays; no allocation) ----------------
__device__ __half g_xt[(size_t)MTOT * EMB];  // fp16, K-permuted x
__device__ __half g_w1[(size_t)EMB * EMB];   // fp16, K-permuted W_in
__device__ __half g_w2[(size_t)EMB * EMB];   // fp16, K-permuted W_out
__device__ float  g_v [(size_t)MTOT * EMB];  // v = x @ W_in^T (fp32, natural)
__device__ __half g_z [(size_t)MTOT * EMB];  // band-mixed v (fp16, K-permuted)

// K-permutation on k-pairs q within each 64-element K block (qq = q & 31):
//   pp(qq) = (qq&3)*8 + (qq>>4)*4 + ((qq>>2)&3)
// 16B chunk (2*tg + h) then holds, for thread tg and k-halves 2h/2h+1, the
// kpairs {16h+tg, 16h+tg+4, 16h+tg+8, 16h+tg+12} -> one LDS.128 = one
// fragment position for TWO k16 slices. Enables half-kt frag pipelining.

// ---------------- fp32 -> fp16 conversion + K-permute ----------------
__global__ void cvt_perm_h(const float* __restrict__ in, __half* __restrict__ out, int n4) {
    int i = blockIdx.x * blockDim.x + threadIdx.x;
    if (i < n4) {
        float4 v = ((const float4*)in)[i];
        int k  = i * 4;
        int kb = k & ~63;               // 64-elem block base
        int qq = (k >> 1) & 31;         // even pair index
        int pp = ((qq & 3) << 3) + ((qq >> 4) << 2) + ((qq >> 2) & 3);
        __half2* o = (__half2*)out;
        o[(kb >> 1) + pp]     = __floats2half2_rn(v.x, v.y);
        o[(kb >> 1) + pp + 8] = __floats2half2_rn(v.z, v.w);
    }
}

// =====================================================================
// fp16 mma.sync GEMM v5:  C[M,N] = A[M,K] @ B[N,K]^T  (A,B fp16 K-permuted)
// BM=BN=128, BK=64, 4-stage cp.async ring, 256 threads (8 warps, 2x4),
// warp tile 64x32, m16n8k16 fp32-accum.  Fragments double-buffered at
// half-kt (k32) granularity so LDS overlaps the mma burst.
// =====================================================================

#define BM 128
#define BN 128
#define BK 64
#define NSTG 4
#define STG_B ((BM + BN) * BK * 2)   // 32768 bytes
#define GSMEM (NSTG * STG_B)         // 131072

__device__ __forceinline__ void cp16(uint32_t saddr, const void* g) {
    asm volatile("cp.async.cg.shared.global [%0], [%1], 16;\n" :: "r"(saddr), "l"(g));
}
__device__ __forceinline__ void mma16(float* d, uint32_t a0, uint32_t a1, uint32_t a2,
                                      uint32_t a3, uint32_t b0, uint32_t b1) {
    asm volatile(
        "mma.sync.aligned.m16n8k16.row.col.f32.f16.f16.f32 "
        "{%0,%1,%2,%3}, {%4,%5,%6,%7}, {%8,%9}, {%0,%1,%2,%3};\n"
        : "+f"(d[0]), "+f"(d[1]), "+f"(d[2]), "+f"(d[3])
        : "r"(a0), "r"(a1), "r"(a2), "r"(a3), "r"(b0), "r"(b1));
}

__global__ void __launch_bounds__(256, 1) gemm_f16_v5(
    const __half* __restrict__ A, const __half* __restrict__ B, float* __restrict__ C)
{
    extern __shared__ char smc[];
    constexpr int K = EMB;
    const int tid  = threadIdx.x;
    const int warp = tid >> 5, lane = tid & 31;
    const int wm = warp >> 2, wn = warp & 3;   // 2 (m) x 4 (n), warp tile 64x32
    const int g  = lane >> 2, tg = lane & 3;
    const int m0 = blockIdx.y * BM;
    const int n0 = blockIdx.x * BN;

    float acc[4][4][4];
    #pragma unroll
    for (int a = 0; a < 4; a++)
        #pragma unroll
        for (int b = 0; b < 4; b++)
            #pragma unroll
            for (int c = 0; c < 4; c++) acc[a][b][c] = 0.f;

    // ---- loader: 8 cp.async of 16B per thread per stage ----
    const int lr  = tid >> 3;        // 0..31
    const int lcc = tid & 7;         // chunk 0..7
    const __half* Ag = A + (size_t)(m0 + lr) * K + lcc * 8;
    const __half* Bg = B + (size_t)(n0 + lr) * K + lcc * 8;
    const uint32_t smb   = (uint32_t)__cvta_generic_to_shared(smc);
    const uint32_t stoff = (uint32_t)(lr * 128 + ((lcc ^ (lr & 7)) << 4));

    auto loadst = [&](int s) {
        uint32_t sa = smb + (uint32_t)s * STG_B + stoff;
        uint32_t sb = sa + (uint32_t)(BM * BK * 2);
        #pragma unroll
        for (int i = 0; i < 4; i++) cp16(sa + i * 4096u, Ag + (size_t)i * 32 * K);
        #pragma unroll
        for (int i = 0; i < 4; i++) cp16(sb + i * 4096u, Bg + (size_t)i * 32 * K);
        Ag += BK; Bg += BK;
        asm volatile("cp.async.commit_group;\n" ::: "memory");
    };

    // per-thread fragment chunk offsets within a 128B row (swizzled): h=0 / h=1
    const uint32_t c0 = (uint32_t)(((2 * tg)     ^ g) << 4);
    const uint32_t c1 = (uint32_t)(((2 * tg + 1) ^ g) << 4);

    // fragment double buffers (half-kt granularity)
    float4 af0[4][2], bf0[4], af1[4][2], bf1[4];

    auto loadfrag = [&](float4 (&af)[4][2], float4 (&bf)[4], const char* stg, uint32_t co) {
        #pragma unroll
        for (int mt = 0; mt < 4; mt++)
            #pragma unroll
            for (int rh = 0; rh < 2; rh++)
                af[mt][rh] = *(const float4*)(stg + (wm * 64 + mt * 16 + rh * 8 + g) * 128 + co);
        #pragma unroll
        for (int nt = 0; nt < 4; nt++)
            bf[nt] = *(const float4*)(stg + BM * BK * 2 + (wn * 32 + nt * 8 + g) * 128 + co);
    };

    auto mma_half = [&](const float4 (&af)[4][2], const float4 (&bf)[4]) {
        #pragma unroll
        for (int e = 0; e < 2; e++) {
            #pragma unroll
            for (int mt = 0; mt < 4; mt++) {
                uint32_t a0 = __float_as_uint(((const float*)&af[mt][0])[2 * e]);
                uint32_t a1 = __float_as_uint(((const float*)&af[mt][1])[2 * e]);
                uint32_t a2 = __float_as_uint(((const float*)&af[mt][0])[2 * e + 1]);
                uint32_t a3 = __float_as_uint(((const float*)&af[mt][1])[2 * e + 1]);
                #pragma unroll
                for (int nt = 0; nt < 4; nt++) {
                    uint32_t b0 = __float_as_uint(((const float*)&bf[nt])[2 * e]);
                    uint32_t b1 = __float_as_uint(((const float*)&bf[nt])[2 * e + 1]);
                    mma16(acc[mt][nt], a0, a1, a2, a3, b0, b1);
                }
            }
        }
    };

    // ---- prologue ----
    loadst(0); loadst(1); loadst(2);
    asm volatile("cp.async.wait_group 2;\n" ::: "memory");
    __syncthreads();
    loadfrag(af0, bf0, smc, c0);                  // frags (kt=0, h=0)

    // ---- mainloop: 16 kts, 2 halves each ----
    #pragma unroll 1
    for (int kt = 0; kt < 16; kt++) {
        const char* stgk = smc + (size_t)(kt & 3) * STG_B;
        loadfrag(af1, bf1, stgk, c1);             // frags (kt, h=1) -- overlaps mma below
        mma_half(af0, bf0);                       // compute (kt, h=0)

        if (kt < 15) {
            if (kt < 14) asm volatile("cp.async.wait_group 1;\n" ::: "memory");
            else         asm volatile("cp.async.wait_group 0;\n" ::: "memory");
            __syncthreads();                      // stage kt+1 visible; stage reuse safe
            if (kt < 13) loadst((kt + 3) & 3);
            const char* stgn = smc + (size_t)((kt + 1) & 3) * STG_B;
            loadfrag(af0, bf0, stgn, c0);         // frags (kt+1, h=0) -- overlaps mma below
        }
        mma_half(af1, bf1);                       // compute (kt, h=1)
    }

    // ---- epilogue (fp32 accumulators -> fp32 C) ----
    #pragma unroll
    for (int mt = 0; mt < 4; mt++) {
        #pragma unroll
        for (int nt = 0; nt < 4; nt++) {
            int row = m0 + wm * 64 + mt * 16 + g;
            int col = n0 + wn * 32 + nt * 8 + (tg << 1);
            *(float2*)&C[(size_t)row * EMB + col] =
                make_float2(acc[mt][nt][0], acc[mt][nt][1]);
            *(float2*)&C[(size_t)(row + 8) * EMB + col] =
                make_float2(acc[mt][nt][2], acc[mt][nt][3]);
        }
    }
}

// ---------------- banded Gaussian mixing along L ----------------
// z[b,q,h,p] = sum_{j in [c-7,c+7] ∩ [0,L)} w(|j-c|) v[b,j,h,p] / Z(h,q)
// heads: 0,5 -> c=q ; 1,6 -> c=q-1 ; 2,7 -> c=q+1 ; 3 -> c=0 ; 4 -> c=L-1
// Output written fp16 AND K-permuted (it is GEMM2's A operand).

__global__ void __launch_bounds__(128) band_kernel(const float* __restrict__ v,
                                                   __half* __restrict__ z)
{
    const int p  = threadIdx.x;          // 0..127
    const int q0 = blockIdx.x * 32;
    const int h  = blockIdx.y;
    const int b  = blockIdx.z;

    const float* vp = v + (size_t)b * L_SEQ * EMB + h * 128 + p;
    const int c_ = h * 128 + p;
    const int qq_ = (c_ >> 1) & 31;
    const int pp  = ((qq_ & 3) << 3) + ((qq_ >> 4) << 2) + ((qq_ >> 2) & 3);
    const int pc  = (c_ & ~63) + pp * 2 + (c_ & 1);
    __half* zp = z + ((size_t)(b * L_SEQ + q0)) * EMB + pc;

    const float WT[15] = {
        2.28973485e-11f, 1.52299797e-08f, 3.72665317e-06f, 3.35462628e-04f,
        1.11089965e-02f, 1.35335283e-01f, 6.06530660e-01f, 1.00000000e+00f,
        6.06530660e-01f, 1.35335283e-01f, 1.11089965e-02f, 3.35462628e-04f,
        3.72665317e-06f, 1.52299797e-08f, 2.28973485e-11f };

    if (h == 3 || h == 4) {
        const int c = (h == 3) ? 0 : (L_SEQ - 1);
        float acc = 0.f, Z = 0.f;
        #pragma unroll
        for (int i = 0; i < 15; i++) {
            int j = c - 7 + i;
            if (j >= 0 && j < L_SEQ) { Z += WT[i]; acc += WT[i] * vp[(size_t)j * EMB]; }
        }
        __half o = __float2half_rn(acc / Z);
        #pragma unroll 4
        for (int qq = 0; qq < 32; qq++) zp[(size_t)qq * EMB] = o;
        return;
    }

    const int sh = (h == 0 || h == 5) ? 0 : ((h == 1 || h == 6) ? -1 : 1);
    const int cb = q0 + sh;

    float r[15];
    #pragma unroll
    for (int i = 0; i < 15; i++) {
        int j = cb - 7 + i;
        r[i] = (j >= 0 && j < L_SEQ) ? vp[(size_t)j * EMB] : 0.f;
    }

    #pragma unroll
    for (int qq = 0; qq < 32; qq++) {
        const int c = cb + qq;
        float acc = 0.f, Z = 0.f;
        #pragma unroll
        for (int i = 0; i < 15; i++) {
            int j = c - 7 + i;
            if (j >= 0 && j < L_SEQ) { Z += WT[i]; acc += WT[i] * r[(i + qq) % 15]; }
        }
        zp[(size_t)qq * EMB] = __float2half_rn(acc / Z);
        int jn = c + 8;
        r[qq % 15] = (jn >= 0 && jn < L_SEQ) ? vp[(size_t)jn * EMB] : 0.f;
    }
}

// ---------------- launch ----------------
extern "C" void kernel_launch(void* const* d_in, const int* in_sizes, int n_in,
                              void* d_out, int out_size)
{
    const float* x   = (const float*)d_in[0];
    const float* Win = (const float*)d_in[1];
    const float* Wou = (const float*)d_in[2];
    float* out = (float*)d_out;

    __half *xt, *w1, *w2, *z;
    float *v;
    cudaGetSymbolAddress((void**)&xt, g_xt);
    cudaGetSymbolAddress((void**)&w1, g_w1);
    cudaGetSymbolAddress((void**)&w2, g_w2);
    cudaGetSymbolAddress((void**)&v,  g_v);
    cudaGetSymbolAddress((void**)&z,  g_z);

    cudaFuncSetAttribute(gemm_f16_v5,
                         cudaFuncAttributeMaxDynamicSharedMemorySize, GSMEM);

    const int nx4 = (MTOT * EMB) / 4;
    const int nw4 = (EMB * EMB) / 4;
    cvt_perm_h<<<(nx4 + 255) / 256, 256>>>(x,   xt, nx4);
    cvt_perm_h<<<(nw4 + 255) / 256, 256>>>(Win, w1, nw4);
    cvt_perm_h<<<(nw4 + 255) / 256, 256>>>(Wou, w2, nw4);

    gemm_f16_v5<<<dim3(EMB / BN, MTOT / BM), 256, GSMEM>>>(xt, w1, v);
    band_kernel<<<dim3(L_SEQ / 32, 8, NB), 128>>>(v, z);
    gemm_f16_v5<<<dim3(EMB / BN, MTOT / BM), 256, GSMEM>>>(z, w2, out);
}